// round 15
// baseline (speedup 1.0000x reference)
#include <cuda_runtime.h>
#include <cuda_fp16.h>
#include <cstdint>

// ============================================================================
// PairwiseMLPLinkPredictor — HMMA + LDG fragment weights, 4 CTAs/SM.
//   4 CTAs/SM x 256 threads, TILE=32 pairs/CTA, 64 regs, 32 warps/SM.
//   Same optimal warp tiles as R13 (L1 32x32, L2 32x16); finer-grained
//   cross-CTA phase overlap keeps the LSU pipe saturated.
//   W1/W2 as pre-packed mma B-fragment images in global (L1D-cached LDG.128).
// ============================================================================

#define NTH    256
#define TILE   32

// ---- SMEM layout (bytes), 18432 per CTA -> 4 CTAs/SM ----
#define OFF_F     0        // 16384 : feats/h1 [32][256] f16 swizzled (512B rows)
#define OFF_B1    16384    // 1024
#define OFF_PART  17408    // 1024  : [8 ngroups][32 rows]
#define SMEM_BYTES 18432

// feats tile [rows][256] f16, 512B rows, 32 x 16B chunks, XOR-(r&7) swizzle
__host__ __device__ __forceinline__ uint32_t timg(int r, int k) {
    return (uint32_t)(r * 512 + ((((k >> 3) ^ (r & 7)) & 31) << 4) + ((k & 7) << 1));
}

// ---- fragment-ordered weight images (R11-validated packing) ----
__device__ __align__(1024) unsigned char g_W1f[131072]; // [ks16][nblk16][lane32] uint4
__device__ __align__(1024) unsigned char g_W2f[65536];  // [ks16][nblk 8][lane32] uint4
__device__ int g_is32;                                  // edge_pairs dtype flag

// ---------------------------------------------------------------------------
__device__ __forceinline__ uint32_t smem_u32(const void* p) {
    uint32_t a;
    asm("{ .reg .u64 t; cvta.to.shared.u64 t, %1; cvt.u32.u64 %0, t; }" : "=r"(a) : "l"(p));
    return a;
}
__device__ __forceinline__ void ldsm_x4(uint32_t r[4], uint32_t addr) {
    asm volatile("ldmatrix.sync.aligned.m8n8.x4.shared.b16 {%0,%1,%2,%3}, [%4];"
                 : "=r"(r[0]), "=r"(r[1]), "=r"(r[2]), "=r"(r[3]) : "r"(addr));
}
__device__ __forceinline__ void mma16816(float c[4], const uint32_t a[4],
                                         uint32_t b0, uint32_t b1) {
    asm volatile("mma.sync.aligned.m16n8k16.row.col.f32.f16.f16.f32 "
                 "{%0,%1,%2,%3}, {%4,%5,%6,%7}, {%8,%9}, {%0,%1,%2,%3};"
                 : "+f"(c[0]), "+f"(c[1]), "+f"(c[2]), "+f"(c[3])
                 : "r"(a[0]), "r"(a[1]), "r"(a[2]), "r"(a[3]), "r"(b0), "r"(b1));
}
__device__ __forceinline__ uint32_t pack_h2(float lo, float hi) {
    union { __half2 h; uint32_t u; } p;
    p.h = __floats2half2_rn(lo, hi);
    return p.u;
}

// ---------------------------------------------------------------------------
// Prep: build fragment images + dtype flag (R11/R13-validated packing).
// ---------------------------------------------------------------------------
__global__ void prep_kernel(const float* __restrict__ W1, const float* __restrict__ W2,
                            const void* __restrict__ ep) {
    const int i = blockIdx.x * blockDim.x + threadIdx.x;
    if (i < 8192) {   // W1 frags
        const int ks = i >> 9, nblk = (i >> 5) & 15, l = i & 31;
        const int k0 = ks * 16 + 2 * (l & 3);
        const int n0 = nblk * 16 + (l >> 2);
        uint4 v;
        v.x = pack_h2(W1[(k0)     * 256 + n0],     W1[(k0 + 1) * 256 + n0]);
        v.y = pack_h2(W1[(k0 + 8) * 256 + n0],     W1[(k0 + 9) * 256 + n0]);
        v.z = pack_h2(W1[(k0)     * 256 + n0 + 8], W1[(k0 + 1) * 256 + n0 + 8]);
        v.w = pack_h2(W1[(k0 + 8) * 256 + n0 + 8], W1[(k0 + 9) * 256 + n0 + 8]);
        *(uint4*)(g_W1f + (size_t)i * 16) = v;
    }
    if (i < 4096) {   // W2 frags
        const int ks = i >> 8, nblk = (i >> 5) & 7, l = i & 31;
        const int k0 = ks * 16 + 2 * (l & 3);
        const int n0 = nblk * 16 + (l >> 2);
        uint4 v;
        v.x = pack_h2(W2[(k0)     * 128 + n0],     W2[(k0 + 1) * 128 + n0]);
        v.y = pack_h2(W2[(k0 + 8) * 128 + n0],     W2[(k0 + 9) * 128 + n0]);
        v.z = pack_h2(W2[(k0)     * 128 + n0 + 8], W2[(k0 + 1) * 128 + n0 + 8]);
        v.w = pack_h2(W2[(k0 + 8) * 128 + n0 + 8], W2[(k0 + 9) * 128 + n0 + 8]);
        *(uint4*)(g_W2f + (size_t)i * 16) = v;
    }
    // dtype probe: int64 edge_pairs -> odd int32 words of first 1KB all zero
    if (blockIdx.x == 0 && threadIdx.x < 128) {
        const int v = ((const int*)ep)[2 * threadIdx.x + 1];
        const int any = __syncthreads_or(v != 0);
        if (threadIdx.x == 0) g_is32 = any;
    }
}

// ---------------------------------------------------------------------------
__global__ void __launch_bounds__(NTH, 4)
pairmlp_ldg4_kernel(const float* __restrict__ x,
                    const float* __restrict__ b1, const float* __restrict__ b2,
                    const float* __restrict__ W3, const float* __restrict__ b3,
                    const void*  __restrict__ ep, float* __restrict__ out, int E)
{
    extern __shared__ char smem[];
    const uint32_t sb = smem_u32(smem);
    const int tid = threadIdx.x, w = tid >> 5, lane = tid & 31;
    const int g = lane >> 2, tig = lane & 3;
    const long long e0 = (long long)blockIdx.x * TILE;

    float* sB1 = (float*)(smem + OFF_B1);
    float* sPart = (float*)(smem + OFF_PART);

    const bool is32 = (g_is32 != 0);
    sB1[tid] = b1[tid];

    // ---- gather + product -> fp16 feats (coalesced: 256B spans per pair) ----
    {
        const int p = tid >> 3, sub = tid & 7;      // 32 pairs x 8 threads
        const long long e = e0 + p;
        long long ia = 0, ib = 0;
        if (e < (long long)E) {
            if (is32) { ia = ((const int*)ep)[2 * e];       ib = ((const int*)ep)[2 * e + 1]; }
            else      { ia = ((const long long*)ep)[2 * e]; ib = ((const long long*)ep)[2 * e + 1]; }
        }
        const float* xa = x + (size_t)ia * 256;
        const float* xb = x + (size_t)ib * 256;
        #pragma unroll
        for (int jj = 0; jj < 8; jj++) {
            const int k = jj * 32 + sub * 4;         // 8 lanes -> contiguous 256B
            float4 a = __ldg((const float4*)(xa + k));
            float4 b = __ldg((const float4*)(xb + k));
            union { __half2 h; uint32_t u; } q0, q1;
            q0.h = __floats2half2_rn(a.x * b.x, a.y * b.y);
            q1.h = __floats2half2_rn(a.z * b.z, a.w * b.w);
            *(uint2*)(smem + OFF_F + timg(p, k)) = make_uint2(q0.u, q1.u);
        }
    }

    // warp geometry: single m-group (TILE=32), wn = w in 0..7
    const int arow0 = ((lane >> 3) & 1) * 8 + (lane & 7);
    const int acsel = lane >> 4;
    const uint32_t aB = sb + OFF_F;

    __syncthreads();       // feats + b1 staged

    // ================= layer 1: 32x256x256, warp 32x32, B via LDG ============
    float acc1[2][4][4];
    #pragma unroll
    for (int mi = 0; mi < 2; mi++)
        #pragma unroll
        for (int ni = 0; ni < 4; ni++)
            #pragma unroll
            for (int v = 0; v < 4; v++) acc1[mi][ni][v] = 0.0f;

    {
        const uint4* f0 = (const uint4*)(g_W1f) + ((size_t)(2 * w) * 32 + lane);
        #pragma unroll
        for (int ks = 0; ks < 16; ks++) {
            uint32_t af[2][4];
            #pragma unroll
            for (int mi = 0; mi < 2; mi++) {
                const int r = mi * 16 + arow0;
                ldsm_x4(af[mi], aB + r * 512 + ((((2 * ks + acsel) ^ (r & 7)) & 31) << 4));
            }
            #pragma unroll
            for (int nb = 0; nb < 2; nb++) {
                const uint4 bv = __ldg(f0 + ((size_t)ks * 16 + nb) * 32);
                #pragma unroll
                for (int mi = 0; mi < 2; mi++) {
                    mma16816(acc1[mi][nb * 2 + 0], af[mi], bv.x, bv.y);
                    mma16816(acc1[mi][nb * 2 + 1], af[mi], bv.z, bv.w);
                }
            }
        }
    }
    __syncthreads();       // all warps done reading feats

    // ---- epilogue 1: h1 = fp16(relu(acc1 + b1)) -> feats buffer ----
    #pragma unroll
    for (int mi = 0; mi < 2; mi++) {
        const int r0 = mi * 16 + g, r1 = r0 + 8;
        #pragma unroll
        for (int ni = 0; ni < 4; ni++) {
            const int c0 = w * 32 + ni * 8 + 2 * tig;
            const float2 bb = *(const float2*)&sB1[c0];
            union { __half2 h; uint32_t u; } lo, hi;
            lo.h = __floats2half2_rn(fmaxf(acc1[mi][ni][0] + bb.x, 0.0f),
                                     fmaxf(acc1[mi][ni][1] + bb.y, 0.0f));
            hi.h = __floats2half2_rn(fmaxf(acc1[mi][ni][2] + bb.x, 0.0f),
                                     fmaxf(acc1[mi][ni][3] + bb.y, 0.0f));
            *(uint32_t*)(smem + OFF_F + timg(r0, c0)) = lo.u;
            *(uint32_t*)(smem + OFF_F + timg(r1, c0)) = hi.u;
        }
    }
    __syncthreads();       // h1 visible

    // ================= layer 2: 32x128x256, warp 32x16, B via LDG ============
    float acc2[2][2][4];
    #pragma unroll
    for (int mi = 0; mi < 2; mi++)
        #pragma unroll
        for (int nb = 0; nb < 2; nb++)
            #pragma unroll
            for (int v = 0; v < 4; v++) acc2[mi][nb][v] = 0.0f;

    {
        const uint4* f2 = (const uint4*)(g_W2f) + ((size_t)w * 32 + lane);
        #pragma unroll
        for (int ks = 0; ks < 16; ks++) {
            uint32_t af[2][4];
            #pragma unroll
            for (int mi = 0; mi < 2; mi++) {
                const int r = mi * 16 + arow0;
                ldsm_x4(af[mi], aB + r * 512 + ((((2 * ks + acsel) ^ (r & 7)) & 31) << 4));
            }
            const uint4 bv = __ldg(f2 + (size_t)ks * 8 * 32);
            #pragma unroll
            for (int mi = 0; mi < 2; mi++) {
                mma16816(acc2[mi][0], af[mi], bv.x, bv.y);
                mma16816(acc2[mi][1], af[mi], bv.z, bv.w);
            }
        }
    }

    // ---- layer 3: out = relu(D2 + b2) . W3 + b3 ----
    {
        const int c0 = w * 16 + 2 * tig;
        const float2 b2r0 = __ldg((const float2*)(b2 + c0));
        const float2 b2r1 = __ldg((const float2*)(b2 + c0 + 8));
        const float2 w3r0 = __ldg((const float2*)(W3 + c0));
        const float2 w3r1 = __ldg((const float2*)(W3 + c0 + 8));
        #pragma unroll
        for (int mi = 0; mi < 2; mi++) {
            float s0 = fmaxf(acc2[mi][0][0] + b2r0.x, 0.0f) * w3r0.x
                     + fmaxf(acc2[mi][0][1] + b2r0.y, 0.0f) * w3r0.y
                     + fmaxf(acc2[mi][1][0] + b2r1.x, 0.0f) * w3r1.x
                     + fmaxf(acc2[mi][1][1] + b2r1.y, 0.0f) * w3r1.y;
            float s1 = fmaxf(acc2[mi][0][2] + b2r0.x, 0.0f) * w3r0.x
                     + fmaxf(acc2[mi][0][3] + b2r0.y, 0.0f) * w3r0.y
                     + fmaxf(acc2[mi][1][2] + b2r1.x, 0.0f) * w3r1.x
                     + fmaxf(acc2[mi][1][3] + b2r1.y, 0.0f) * w3r1.y;
            s0 += __shfl_xor_sync(0xffffffffu, s0, 1);
            s0 += __shfl_xor_sync(0xffffffffu, s0, 2);
            s1 += __shfl_xor_sync(0xffffffffu, s1, 1);
            s1 += __shfl_xor_sync(0xffffffffu, s1, 2);
            if (tig == 0) {
                const int r0 = mi * 16 + g;
                sPart[w * 32 + r0]     = s0;
                sPart[w * 32 + r0 + 8] = s1;
            }
        }
    }
    __syncthreads();

    if (tid < 32) {
        const long long e = e0 + tid;
        if (e < E) {
            float s = __ldg(b3);
            #pragma unroll
            for (int j = 0; j < 8; j++) s += sPart[j * 32 + tid];
            out[e] = s;
        }
    }
}

// ---------------------------------------------------------------------------
extern "C" void kernel_launch(void* const* d_in, const int* in_sizes, int n_in,
                              void* d_out, int out_size)
{
    const float* x  = (const float*)d_in[0];
    const float* W1 = (const float*)d_in[1];
    const float* b1 = (const float*)d_in[2];
    const float* W2 = (const float*)d_in[3];
    const float* b2 = (const float*)d_in[4];
    const float* W3 = (const float*)d_in[5];
    const float* b3 = (const float*)d_in[6];
    // d_in[7] = edge_index (unused)
    const void*  ep = d_in[8];
    float* out = (float*)d_out;

    const int E = out_size;
    prep_kernel<<<32, 256>>>(W1, W2, ep);

    cudaFuncSetAttribute(pairmlp_ldg4_kernel,
                         cudaFuncAttributeMaxDynamicSharedMemorySize, SMEM_BYTES);
    const int nblocks = (E + TILE - 1) / TILE;
    pairmlp_ldg4_kernel<<<nblocks, NTH, SMEM_BYTES>>>(x, b1, b2, W3, b3, ep, out, E);
}

// round 16
// speedup vs baseline: 1.5029x; 1.5029x over previous
#include <cuda_runtime.h>
#include <cuda_fp16.h>
#include <cstdint>

// ============================================================================
// PairwiseMLPLinkPredictor — R13 config + L1 cache-policy hints.
//   2 CTAs/SM x 512 threads, TILE=64 pairs/CTA, 64 regs (proven 676us base).
//   Weights (fragment images): LDG evict_last  -> pinned in L1D.
//   Gather (random x rows):    LDG evict_first -> no weight eviction.
//   Output: st.global.cs (streaming).
// ============================================================================

#define NTH    512
#define TILE   64

// ---- SMEM layout (bytes), 35840 per CTA -> 2 CTAs/SM, big L1D carveout ----
#define OFF_F     0        // 32768 : feats/h1 [64][256] f16 swizzled (512B rows)
#define OFF_B1    32768    // 1024
#define OFF_PART  33792    // 2048  : [8 ngroups][64 rows]
#define SMEM_BYTES 35840

// feats tile [rows][256] f16, 512B rows, 32 x 16B chunks, XOR-(r&7) swizzle
__host__ __device__ __forceinline__ uint32_t timg(int r, int k) {
    return (uint32_t)(r * 512 + ((((k >> 3) ^ (r & 7)) & 31) << 4) + ((k & 7) << 1));
}

// ---- fragment-ordered weight images (R11-validated packing) ----
__device__ __align__(1024) unsigned char g_W1f[131072]; // [ks16][nblk16][lane32] uint4
__device__ __align__(1024) unsigned char g_W2f[65536];  // [ks16][nblk 8][lane32] uint4
__device__ int g_is32;                                  // edge_pairs dtype flag

// ---------------------------------------------------------------------------
__device__ __forceinline__ uint32_t smem_u32(const void* p) {
    uint32_t a;
    asm("{ .reg .u64 t; cvta.to.shared.u64 t, %1; cvt.u32.u64 %0, t; }" : "=r"(a) : "l"(p));
    return a;
}
__device__ __forceinline__ void ldsm_x4(uint32_t r[4], uint32_t addr) {
    asm volatile("ldmatrix.sync.aligned.m8n8.x4.shared.b16 {%0,%1,%2,%3}, [%4];"
                 : "=r"(r[0]), "=r"(r[1]), "=r"(r[2]), "=r"(r[3]) : "r"(addr));
}
__device__ __forceinline__ void mma16816(float c[4], const uint32_t a[4],
                                         uint32_t b0, uint32_t b1) {
    asm volatile("mma.sync.aligned.m16n8k16.row.col.f32.f16.f16.f32 "
                 "{%0,%1,%2,%3}, {%4,%5,%6,%7}, {%8,%9}, {%0,%1,%2,%3};"
                 : "+f"(c[0]), "+f"(c[1]), "+f"(c[2]), "+f"(c[3])
                 : "r"(a[0]), "r"(a[1]), "r"(a[2]), "r"(a[3]), "r"(b0), "r"(b1));
}
// weight fragment load: read-only + keep resident in L1D
__device__ __forceinline__ uint4 ldg_w(const uint4* p) {
    uint4 v;
    asm("ld.global.nc.L1::evict_last.v4.u32 {%0,%1,%2,%3}, [%4];"
        : "=r"(v.x), "=r"(v.y), "=r"(v.z), "=r"(v.w) : "l"(p));
    return v;
}
// gather load: read-only + transient (don't evict weights)
__device__ __forceinline__ float4 ldg_x(const float* p) {
    float4 v;
    asm("ld.global.nc.L1::evict_first.v4.f32 {%0,%1,%2,%3}, [%4];"
        : "=f"(v.x), "=f"(v.y), "=f"(v.z), "=f"(v.w) : "l"(p));
    return v;
}
__device__ __forceinline__ uint32_t pack_h2(float lo, float hi) {
    union { __half2 h; uint32_t u; } p;
    p.h = __floats2half2_rn(lo, hi);
    return p.u;
}

// ---------------------------------------------------------------------------
// Prep: build fragment images + dtype flag (R11/R13-validated packing).
// ---------------------------------------------------------------------------
__global__ void prep_kernel(const float* __restrict__ W1, const float* __restrict__ W2,
                            const void* __restrict__ ep) {
    const int i = blockIdx.x * blockDim.x + threadIdx.x;
    if (i < 8192) {   // W1 frags
        const int ks = i >> 9, nblk = (i >> 5) & 15, l = i & 31;
        const int k0 = ks * 16 + 2 * (l & 3);
        const int n0 = nblk * 16 + (l >> 2);
        uint4 v;
        v.x = pack_h2(W1[(k0)     * 256 + n0],     W1[(k0 + 1) * 256 + n0]);
        v.y = pack_h2(W1[(k0 + 8) * 256 + n0],     W1[(k0 + 9) * 256 + n0]);
        v.z = pack_h2(W1[(k0)     * 256 + n0 + 8], W1[(k0 + 1) * 256 + n0 + 8]);
        v.w = pack_h2(W1[(k0 + 8) * 256 + n0 + 8], W1[(k0 + 9) * 256 + n0 + 8]);
        *(uint4*)(g_W1f + (size_t)i * 16) = v;
    }
    if (i < 4096) {   // W2 frags
        const int ks = i >> 8, nblk = (i >> 5) & 7, l = i & 31;
        const int k0 = ks * 16 + 2 * (l & 3);
        const int n0 = nblk * 16 + (l >> 2);
        uint4 v;
        v.x = pack_h2(W2[(k0)     * 128 + n0],     W2[(k0 + 1) * 128 + n0]);
        v.y = pack_h2(W2[(k0 + 8) * 128 + n0],     W2[(k0 + 9) * 128 + n0]);
        v.z = pack_h2(W2[(k0)     * 128 + n0 + 8], W2[(k0 + 1) * 128 + n0 + 8]);
        v.w = pack_h2(W2[(k0 + 8) * 128 + n0 + 8], W2[(k0 + 9) * 128 + n0 + 8]);
        *(uint4*)(g_W2f + (size_t)i * 16) = v;
    }
    // dtype probe: int64 edge_pairs -> odd int32 words of first 1KB all zero
    if (blockIdx.x == 0 && threadIdx.x < 128) {
        const int v = ((const int*)ep)[2 * threadIdx.x + 1];
        const int any = __syncthreads_or(v != 0);
        if (threadIdx.x == 0) g_is32 = any;
    }
}

// ---------------------------------------------------------------------------
__global__ void __launch_bounds__(NTH, 2)
pairmlp_hint_kernel(const float* __restrict__ x,
                    const float* __restrict__ b1, const float* __restrict__ b2,
                    const float* __restrict__ W3, const float* __restrict__ b3,
                    const void*  __restrict__ ep, float* __restrict__ out, int E)
{
    extern __shared__ char smem[];
    const uint32_t sb = smem_u32(smem);
    const int tid = threadIdx.x, w = tid >> 5, lane = tid & 31;
    const int g = lane >> 2, tig = lane & 3;
    const long long e0 = (long long)blockIdx.x * TILE;

    float* sB1 = (float*)(smem + OFF_B1);
    float* sPart = (float*)(smem + OFF_PART);

    const bool is32 = (g_is32 != 0);
    if (tid < 256) sB1[tid] = b1[tid];

    // ---- gather + product -> fp16 feats (coalesced 256B spans, evict_first) --
    {
        const int p = tid >> 3, sub = tid & 7;
        const long long e = e0 + p;
        long long ia = 0, ib = 0;
        if (e < (long long)E) {
            if (is32) { ia = ((const int*)ep)[2 * e];       ib = ((const int*)ep)[2 * e + 1]; }
            else      { ia = ((const long long*)ep)[2 * e]; ib = ((const long long*)ep)[2 * e + 1]; }
        }
        const float* xa = x + (size_t)ia * 256;
        const float* xb = x + (size_t)ib * 256;
        #pragma unroll
        for (int jj = 0; jj < 8; jj++) {
            const int k = jj * 32 + sub * 4;         // 8 lanes -> contiguous 256B
            float4 a = ldg_x(xa + k);
            float4 b = ldg_x(xb + k);
            union { __half2 h; uint32_t u; } q0, q1;
            q0.h = __floats2half2_rn(a.x * b.x, a.y * b.y);
            q1.h = __floats2half2_rn(a.z * b.z, a.w * b.w);
            *(uint2*)(smem + OFF_F + timg(p, k)) = make_uint2(q0.u, q1.u);
        }
    }

    // warp geometry (R10/R11/R13-validated)
    const int wm = w & 1, wn = w >> 1;                  // L1: 2m x 8n (warp 32x32)
    const int arow0 = ((lane >> 3) & 1) * 8 + (lane & 7);
    const int acsel = lane >> 4;
    const uint32_t aB = sb + OFF_F;

    __syncthreads();       // feats + b1 staged

    // ================= layer 1: 64x256x256, warp 32x32, B via LDG ============
    float acc1[2][4][4];
    #pragma unroll
    for (int mi = 0; mi < 2; mi++)
        #pragma unroll
        for (int ni = 0; ni < 4; ni++)
            #pragma unroll
            for (int v = 0; v < 4; v++) acc1[mi][ni][v] = 0.0f;

    {
        const uint4* f0 = (const uint4*)(g_W1f) + ((size_t)(2 * wn) * 32 + lane);
        #pragma unroll
        for (int ks = 0; ks < 16; ks++) {
            uint32_t af[2][4];
            #pragma unroll
            for (int mi = 0; mi < 2; mi++) {
                const int r = wm * 32 + mi * 16 + arow0;
                ldsm_x4(af[mi], aB + r * 512 + ((((2 * ks + acsel) ^ (r & 7)) & 31) << 4));
            }
            #pragma unroll
            for (int nb = 0; nb < 2; nb++) {
                const uint4 bv = ldg_w(f0 + ((size_t)ks * 16 + nb) * 32);
                #pragma unroll
                for (int mi = 0; mi < 2; mi++) {
                    mma16816(acc1[mi][nb * 2 + 0], af[mi], bv.x, bv.y);
                    mma16816(acc1[mi][nb * 2 + 1], af[mi], bv.z, bv.w);
                }
            }
        }
    }
    __syncthreads();       // all warps done reading feats

    // ---- epilogue 1: h1 = fp16(relu(acc1 + b1)) -> feats buffer ----
    #pragma unroll
    for (int mi = 0; mi < 2; mi++) {
        const int r0 = wm * 32 + mi * 16 + g, r1 = r0 + 8;
        #pragma unroll
        for (int ni = 0; ni < 4; ni++) {
            const int c0 = wn * 32 + ni * 8 + 2 * tig;
            const float2 bb = *(const float2*)&sB1[c0];
            union { __half2 h; uint32_t u; } lo, hi;
            lo.h = __floats2half2_rn(fmaxf(acc1[mi][ni][0] + bb.x, 0.0f),
                                     fmaxf(acc1[mi][ni][1] + bb.y, 0.0f));
            hi.h = __floats2half2_rn(fmaxf(acc1[mi][ni][2] + bb.x, 0.0f),
                                     fmaxf(acc1[mi][ni][3] + bb.y, 0.0f));
            *(uint32_t*)(smem + OFF_F + timg(r0, c0)) = lo.u;
            *(uint32_t*)(smem + OFF_F + timg(r1, c0)) = hi.u;
        }
    }
    __syncthreads();       // h1 visible

    // ================= layer 2: 64x128x256, warp 32x16, B via LDG ============
    const int wm2 = w & 1, wn2 = w >> 1;               // 2m x 8n
    float acc2[2][2][4];
    #pragma unroll
    for (int mi = 0; mi < 2; mi++)
        #pragma unroll
        for (int nb = 0; nb < 2; nb++)
            #pragma unroll
            for (int v = 0; v < 4; v++) acc2[mi][nb][v] = 0.0f;

    {
        const uint4* f2 = (const uint4*)(g_W2f) + ((size_t)wn2 * 32 + lane);
        #pragma unroll
        for (int ks = 0; ks < 16; ks++) {
            uint32_t af[2][4];
            #pragma unroll
            for (int mi = 0; mi < 2; mi++) {
                const int r = wm2 * 32 + mi * 16 + arow0;
                ldsm_x4(af[mi], aB + r * 512 + ((((2 * ks + acsel) ^ (r & 7)) & 31) << 4));
            }
            const uint4 bv = ldg_w(f2 + (size_t)ks * 8 * 32);
            #pragma unroll
            for (int mi = 0; mi < 2; mi++) {
                mma16816(acc2[mi][0], af[mi], bv.x, bv.y);
                mma16816(acc2[mi][1], af[mi], bv.z, bv.w);
            }
        }
    }

    // ---- layer 3: out = relu(D2 + b2) . W3 + b3 ----
    {
        const int c0 = wn2 * 16 + 2 * tig;
        const float2 b2r0 = __ldg((const float2*)(b2 + c0));
        const float2 b2r1 = __ldg((const float2*)(b2 + c0 + 8));
        const float2 w3r0 = __ldg((const float2*)(W3 + c0));
        const float2 w3r1 = __ldg((const float2*)(W3 + c0 + 8));
        #pragma unroll
        for (int mi = 0; mi < 2; mi++) {
            float s0 = fmaxf(acc2[mi][0][0] + b2r0.x, 0.0f) * w3r0.x
                     + fmaxf(acc2[mi][0][1] + b2r0.y, 0.0f) * w3r0.y
                     + fmaxf(acc2[mi][1][0] + b2r1.x, 0.0f) * w3r1.x
                     + fmaxf(acc2[mi][1][1] + b2r1.y, 0.0f) * w3r1.y;
            float s1 = fmaxf(acc2[mi][0][2] + b2r0.x, 0.0f) * w3r0.x
                     + fmaxf(acc2[mi][0][3] + b2r0.y, 0.0f) * w3r0.y
                     + fmaxf(acc2[mi][1][2] + b2r1.x, 0.0f) * w3r1.x
                     + fmaxf(acc2[mi][1][3] + b2r1.y, 0.0f) * w3r1.y;
            s0 += __shfl_xor_sync(0xffffffffu, s0, 1);
            s0 += __shfl_xor_sync(0xffffffffu, s0, 2);
            s1 += __shfl_xor_sync(0xffffffffu, s1, 1);
            s1 += __shfl_xor_sync(0xffffffffu, s1, 2);
            if (tig == 0) {
                const int r0 = wm2 * 32 + mi * 16 + g;
                sPart[wn2 * 64 + r0]     = s0;
                sPart[wn2 * 64 + r0 + 8] = s1;
            }
        }
    }
    __syncthreads();

    if (tid < 64) {
        const long long e = e0 + tid;
        if (e < E) {
            float s = __ldg(b3);
            #pragma unroll
            for (int j = 0; j < 8; j++) s += sPart[j * 64 + tid];
            asm volatile("st.global.cs.f32 [%0], %1;" :: "l"(out + e), "f"(s) : "memory");
        }
    }
}

// ---------------------------------------------------------------------------
extern "C" void kernel_launch(void* const* d_in, const int* in_sizes, int n_in,
                              void* d_out, int out_size)
{
    const float* x  = (const float*)d_in[0];
    const float* W1 = (const float*)d_in[1];
    const float* b1 = (const float*)d_in[2];
    const float* W2 = (const float*)d_in[3];
    const float* b2 = (const float*)d_in[4];
    const float* W3 = (const float*)d_in[5];
    const float* b3 = (const float*)d_in[6];
    // d_in[7] = edge_index (unused)
    const void*  ep = d_in[8];
    float* out = (float*)d_out;

    const int E = out_size;
    prep_kernel<<<32, 256>>>(W1, W2, ep);

    cudaFuncSetAttribute(pairmlp_hint_kernel,
                         cudaFuncAttributeMaxDynamicSharedMemorySize, SMEM_BYTES);
    const int nblocks = (E + TILE - 1) / TILE;
    pairmlp_hint_kernel<<<nblocks, NTH, SMEM_BYTES>>>(x, b1, b2, W3, b3, ep, out, E);
}

// round 17
// speedup vs baseline: 1.5051x; 1.0014x over previous
#include <cuda_runtime.h>
#include <cuda_fp16.h>
#include <cstdint>

// ============================================================================
// PairwiseMLPLinkPredictor — converged HMMA kernel + latency micro-opts.
//   2 CTAs/SM x 512 threads, TILE=64 pairs/CTA, 64 regs.
//   W1/W2 as pre-packed mma B-fragment images (LDG.128, evict_last).
//   Gather: fused pair-index load + explicit 4-deep LDG batching.
// ============================================================================

#define NTH    512
#define TILE   64

// ---- SMEM layout (bytes), 35840 per CTA -> 2 CTAs/SM ----
#define OFF_F     0        // 32768 : feats/h1 [64][256] f16 swizzled (512B rows)
#define OFF_B1    32768    // 1024
#define OFF_PART  33792    // 2048  : [8 ngroups][64 rows]
#define SMEM_BYTES 35840

// feats tile [rows][256] f16, 512B rows, 32 x 16B chunks, XOR-(r&7) swizzle
__host__ __device__ __forceinline__ uint32_t timg(int r, int k) {
    return (uint32_t)(r * 512 + ((((k >> 3) ^ (r & 7)) & 31) << 4) + ((k & 7) << 1));
}

// ---- fragment-ordered weight images (R11-validated packing) ----
__device__ __align__(1024) unsigned char g_W1f[131072]; // [ks16][nblk16][lane32] uint4
__device__ __align__(1024) unsigned char g_W2f[65536];  // [ks16][nblk 8][lane32] uint4
__device__ int g_is32;                                  // edge_pairs dtype flag

// ---------------------------------------------------------------------------
__device__ __forceinline__ uint32_t smem_u32(const void* p) {
    uint32_t a;
    asm("{ .reg .u64 t; cvta.to.shared.u64 t, %1; cvt.u32.u64 %0, t; }" : "=r"(a) : "l"(p));
    return a;
}
__device__ __forceinline__ void ldsm_x4(uint32_t r[4], uint32_t addr) {
    asm volatile("ldmatrix.sync.aligned.m8n8.x4.shared.b16 {%0,%1,%2,%3}, [%4];"
                 : "=r"(r[0]), "=r"(r[1]), "=r"(r[2]), "=r"(r[3]) : "r"(addr));
}
__device__ __forceinline__ void mma16816(float c[4], const uint32_t a[4],
                                         uint32_t b0, uint32_t b1) {
    asm volatile("mma.sync.aligned.m16n8k16.row.col.f32.f16.f16.f32 "
                 "{%0,%1,%2,%3}, {%4,%5,%6,%7}, {%8,%9}, {%0,%1,%2,%3};"
                 : "+f"(c[0]), "+f"(c[1]), "+f"(c[2]), "+f"(c[3])
                 : "r"(a[0]), "r"(a[1]), "r"(a[2]), "r"(a[3]), "r"(b0), "r"(b1));
}
// weight fragment load: read-only, keep resident in L1D
__device__ __forceinline__ uint4 ldg_w(const uint4* p) {
    uint4 v;
    asm("ld.global.nc.L1::evict_last.v4.u32 {%0,%1,%2,%3}, [%4];"
        : "=r"(v.x), "=r"(v.y), "=r"(v.z), "=r"(v.w) : "l"(p));
    return v;
}
// gather load: read-only, transient
__device__ __forceinline__ float4 ldg_x(const float* p) {
    float4 v;
    asm("ld.global.nc.L1::evict_first.v4.f32 {%0,%1,%2,%3}, [%4];"
        : "=f"(v.x), "=f"(v.y), "=f"(v.z), "=f"(v.w) : "l"(p));
    return v;
}
__device__ __forceinline__ uint32_t pack_h2(float lo, float hi) {
    union { __half2 h; uint32_t u; } p;
    p.h = __floats2half2_rn(lo, hi);
    return p.u;
}

// ---------------------------------------------------------------------------
// Prep: build fragment images + dtype flag (R11/R13-validated packing).
// ---------------------------------------------------------------------------
__global__ void prep_kernel(const float* __restrict__ W1, const float* __restrict__ W2,
                            const void* __restrict__ ep) {
    const int i = blockIdx.x * blockDim.x + threadIdx.x;
    if (i < 8192) {   // W1 frags
        const int ks = i >> 9, nblk = (i >> 5) & 15, l = i & 31;
        const int k0 = ks * 16 + 2 * (l & 3);
        const int n0 = nblk * 16 + (l >> 2);
        uint4 v;
        v.x = pack_h2(W1[(k0)     * 256 + n0],     W1[(k0 + 1) * 256 + n0]);
        v.y = pack_h2(W1[(k0 + 8) * 256 + n0],     W1[(k0 + 9) * 256 + n0]);
        v.z = pack_h2(W1[(k0)     * 256 + n0 + 8], W1[(k0 + 1) * 256 + n0 + 8]);
        v.w = pack_h2(W1[(k0 + 8) * 256 + n0 + 8], W1[(k0 + 9) * 256 + n0 + 8]);
        *(uint4*)(g_W1f + (size_t)i * 16) = v;
    }
    if (i < 4096) {   // W2 frags
        const int ks = i >> 8, nblk = (i >> 5) & 7, l = i & 31;
        const int k0 = ks * 16 + 2 * (l & 3);
        const int n0 = nblk * 16 + (l >> 2);
        uint4 v;
        v.x = pack_h2(W2[(k0)     * 128 + n0],     W2[(k0 + 1) * 128 + n0]);
        v.y = pack_h2(W2[(k0 + 8) * 128 + n0],     W2[(k0 + 9) * 128 + n0]);
        v.z = pack_h2(W2[(k0)     * 128 + n0 + 8], W2[(k0 + 1) * 128 + n0 + 8]);
        v.w = pack_h2(W2[(k0 + 8) * 128 + n0 + 8], W2[(k0 + 9) * 128 + n0 + 8]);
        *(uint4*)(g_W2f + (size_t)i * 16) = v;
    }
    // dtype probe: int64 edge_pairs -> odd int32 words of first 1KB all zero
    if (blockIdx.x == 0 && threadIdx.x < 128) {
        const int v = ((const int*)ep)[2 * threadIdx.x + 1];
        const int any = __syncthreads_or(v != 0);
        if (threadIdx.x == 0) g_is32 = any;
    }
}

// ---------------------------------------------------------------------------
__global__ void __launch_bounds__(NTH, 2)
pairmlp_final_kernel(const float* __restrict__ x,
                     const float* __restrict__ b1, const float* __restrict__ b2,
                     const float* __restrict__ W3, const float* __restrict__ b3,
                     const void*  __restrict__ ep, float* __restrict__ out, int E)
{
    extern __shared__ char smem[];
    const uint32_t sb = smem_u32(smem);
    const int tid = threadIdx.x, w = tid >> 5, lane = tid & 31;
    const int g = lane >> 2, tig = lane & 3;
    const long long e0 = (long long)blockIdx.x * TILE;

    float* sB1 = (float*)(smem + OFF_B1);
    float* sPart = (float*)(smem + OFF_PART);

    const bool is32 = (g_is32 != 0);
    if (tid < 256) sB1[tid] = b1[tid];

    // ---- gather + product -> fp16 feats (fused idx load, 4-deep LDG batch) --
    {
        const int p = tid >> 3, sub = tid & 7;
        const long long e = e0 + p;
        long long ia = 0, ib = 0;
        if (e < (long long)E) {
            if (is32) {
                const int2 v = __ldg((const int2*)ep + e);       // one LDG.64
                ia = v.x; ib = v.y;
            } else {
                const longlong2 v = __ldg((const longlong2*)ep + e);  // one LDG.128
                ia = v.x; ib = v.y;
            }
        }
        const float* xa = x + (size_t)ia * 256;
        const float* xb = x + (size_t)ib * 256;
        #pragma unroll
        for (int jj = 0; jj < 4; jj++) {
            // 4 independent LDG.128 in flight before any math
            const int k0 = jj * 64 + sub * 4;
            const int k1 = k0 + 32;
            float4 a0 = ldg_x(xa + k0);
            float4 a1 = ldg_x(xa + k1);
            float4 c0 = ldg_x(xb + k0);
            float4 c1 = ldg_x(xb + k1);
            union { __half2 h; uint32_t u; } q0, q1, q2, q3;
            q0.h = __floats2half2_rn(a0.x * c0.x, a0.y * c0.y);
            q1.h = __floats2half2_rn(a0.z * c0.z, a0.w * c0.w);
            q2.h = __floats2half2_rn(a1.x * c1.x, a1.y * c1.y);
            q3.h = __floats2half2_rn(a1.z * c1.z, a1.w * c1.w);
            *(uint2*)(smem + OFF_F + timg(p, k0)) = make_uint2(q0.u, q1.u);
            *(uint2*)(smem + OFF_F + timg(p, k1)) = make_uint2(q2.u, q3.u);
        }
    }

    // warp geometry (validated R10..R16)
    const int wm = w & 1, wn = w >> 1;                  // L1: 2m x 8n (warp 32x32)
    const int arow0 = ((lane >> 3) & 1) * 8 + (lane & 7);
    const int acsel = lane >> 4;
    const uint32_t aB = sb + OFF_F;

    __syncthreads();       // feats + b1 staged

    // ================= layer 1: 64x256x256, warp 32x32, B via LDG ============
    float acc1[2][4][4];
    #pragma unroll
    for (int mi = 0; mi < 2; mi++)
        #pragma unroll
        for (int ni = 0; ni < 4; ni++)
            #pragma unroll
            for (int v = 0; v < 4; v++) acc1[mi][ni][v] = 0.0f;

    {
        const uint4* f0 = (const uint4*)(g_W1f) + ((size_t)(2 * wn) * 32 + lane);
        #pragma unroll
        for (int ks = 0; ks < 16; ks++) {
            uint32_t af[2][4];
            #pragma unroll
            for (int mi = 0; mi < 2; mi++) {
                const int r = wm * 32 + mi * 16 + arow0;
                ldsm_x4(af[mi], aB + r * 512 + ((((2 * ks + acsel) ^ (r & 7)) & 31) << 4));
            }
            #pragma unroll
            for (int nb = 0; nb < 2; nb++) {
                const uint4 bv = ldg_w(f0 + ((size_t)ks * 16 + nb) * 32);
                #pragma unroll
                for (int mi = 0; mi < 2; mi++) {
                    mma16816(acc1[mi][nb * 2 + 0], af[mi], bv.x, bv.y);
                    mma16816(acc1[mi][nb * 2 + 1], af[mi], bv.z, bv.w);
                }
            }
        }
    }
    __syncthreads();       // all warps done reading feats

    // ---- epilogue 1: h1 = fp16(relu(acc1 + b1)) -> feats buffer ----
    #pragma unroll
    for (int mi = 0; mi < 2; mi++) {
        const int r0 = wm * 32 + mi * 16 + g, r1 = r0 + 8;
        #pragma unroll
        for (int ni = 0; ni < 4; ni++) {
            const int c0 = wn * 32 + ni * 8 + 2 * tig;
            const float2 bb = *(const float2*)&sB1[c0];
            union { __half2 h; uint32_t u; } lo, hi;
            lo.h = __floats2half2_rn(fmaxf(acc1[mi][ni][0] + bb.x, 0.0f),
                                     fmaxf(acc1[mi][ni][1] + bb.y, 0.0f));
            hi.h = __floats2half2_rn(fmaxf(acc1[mi][ni][2] + bb.x, 0.0f),
                                     fmaxf(acc1[mi][ni][3] + bb.y, 0.0f));
            *(uint32_t*)(smem + OFF_F + timg(r0, c0)) = lo.u;
            *(uint32_t*)(smem + OFF_F + timg(r1, c0)) = hi.u;
        }
    }
    __syncthreads();       // h1 visible

    // ================= layer 2: 64x128x256, warp 32x16, B via LDG ============
    const int wm2 = w & 1, wn2 = w >> 1;               // 2m x 8n
    float acc2[2][2][4];
    #pragma unroll
    for (int mi = 0; mi < 2; mi++)
        #pragma unroll
        for (int nb = 0; nb < 2; nb++)
            #pragma unroll
            for (int v = 0; v < 4; v++) acc2[mi][nb][v] = 0.0f;

    {
        const uint4* f2 = (const uint4*)(g_W2f) + ((size_t)wn2 * 32 + lane);
        #pragma unroll
        for (int ks = 0; ks < 16; ks++) {
            uint32_t af[2][4];
            #pragma unroll
            for (int mi = 0; mi < 2; mi++) {
                const int r = wm2 * 32 + mi * 16 + arow0;
                ldsm_x4(af[mi], aB + r * 512 + ((((2 * ks + acsel) ^ (r & 7)) & 31) << 4));
            }
            const uint4 bv = ldg_w(f2 + (size_t)ks * 8 * 32);
            #pragma unroll
            for (int mi = 0; mi < 2; mi++) {
                mma16816(acc2[mi][0], af[mi], bv.x, bv.y);
                mma16816(acc2[mi][1], af[mi], bv.z, bv.w);
            }
        }
    }

    // ---- layer 3: out = relu(D2 + b2) . W3 + b3 ----
    {
        const int c0 = wn2 * 16 + 2 * tig;
        const float2 b2r0 = __ldg((const float2*)(b2 + c0));
        const float2 b2r1 = __ldg((const float2*)(b2 + c0 + 8));
        const float2 w3r0 = __ldg((const float2*)(W3 + c0));
        const float2 w3r1 = __ldg((const float2*)(W3 + c0 + 8));
        #pragma unroll
        for (int mi = 0; mi < 2; mi++) {
            float s0 = fmaxf(acc2[mi][0][0] + b2r0.x, 0.0f) * w3r0.x
                     + fmaxf(acc2[mi][0][1] + b2r0.y, 0.0f) * w3r0.y
                     + fmaxf(acc2[mi][1][0] + b2r1.x, 0.0f) * w3r1.x
                     + fmaxf(acc2[mi][1][1] + b2r1.y, 0.0f) * w3r1.y;
            float s1 = fmaxf(acc2[mi][0][2] + b2r0.x, 0.0f) * w3r0.x
                     + fmaxf(acc2[mi][0][3] + b2r0.y, 0.0f) * w3r0.y
                     + fmaxf(acc2[mi][1][2] + b2r1.x, 0.0f) * w3r1.x
                     + fmaxf(acc2[mi][1][3] + b2r1.y, 0.0f) * w3r1.y;
            s0 += __shfl_xor_sync(0xffffffffu, s0, 1);
            s0 += __shfl_xor_sync(0xffffffffu, s0, 2);
            s1 += __shfl_xor_sync(0xffffffffu, s1, 1);
            s1 += __shfl_xor_sync(0xffffffffu, s1, 2);
            if (tig == 0) {
                const int r0 = wm2 * 32 + mi * 16 + g;
                sPart[wn2 * 64 + r0]     = s0;
                sPart[wn2 * 64 + r0 + 8] = s1;
            }
        }
    }
    __syncthreads();

    if (tid < 64) {
        const long long e = e0 + tid;
        if (e < E) {
            float s = __ldg(b3);
            #pragma unroll
            for (int j = 0; j < 8; j++) s += sPart[j * 64 + tid];
            out[e] = s;
        }
    }
}

// ---------------------------------------------------------------------------
extern "C" void kernel_launch(void* const* d_in, const int* in_sizes, int n_in,
                              void* d_out, int out_size)
{
    const float* x  = (const float*)d_in[0];
    const float* W1 = (const float*)d_in[1];
    const float* b1 = (const float*)d_in[2];
    const float* W2 = (const float*)d_in[3];
    const float* b2 = (const float*)d_in[4];
    const float* W3 = (const float*)d_in[5];
    const float* b3 = (const float*)d_in[6];
    // d_in[7] = edge_index (unused)
    const void*  ep = d_in[8];
    float* out = (float*)d_out;

    const int E = out_size;
    prep_kernel<<<32, 256>>>(W1, W2, ep);

    cudaFuncSetAttribute(pairmlp_final_kernel,
                         cudaFuncAttributeMaxDynamicSharedMemorySize, SMEM_BYTES);
    const int nblocks = (E + TILE - 1) / TILE;
    pairmlp_final_kernel<<<nblocks, NTH, SMEM_BYTES>>>(x, b1, b2, W3, b3, ep, out, E);
}